// round 3
// baseline (speedup 1.0000x reference)
#include <cuda_runtime.h>
#include <math.h>

// Problem constants
#define T_    512
#define B_    64
#define H_    1024
#define C_    32000
#define SIXH  6144
#define M_    (T_*B_)        // 32768 rows of xin
#define BH    (B_*H_)        // 65536
#define YSIZE (B_*C_)
#define GRID_G 128           // persistent kernel CTAs (<=148 SMs => co-resident)

typedef unsigned long long ull;

// -------- scratch (no cudaMalloc allowed) --------
__device__ float    g_xin[M_*H_];       // xin[t*64+b][n]
__device__ float    g_h[BH];            // current hidden state
__device__ float    g_part[8*BH];       // K-split partial sums: part[ks][b][n]
__device__ volatile unsigned g_flags[GRID_G];  // barrier flags (monotonic epoch values)
__device__ unsigned g_epoch = 0;        // base epoch, advanced once per launch

// packed fp32x2 FMA (Blackwell): d = a*b + c on both lanes
__device__ __forceinline__ ull fma2(ull a, ull b, ull c) {
    ull d;
    asm("fma.rn.f32x2 %0, %1, %2, %3;" : "=l"(d) : "l"(a), "l"(b), "l"(c));
    return d;
}

// -------- flat flag grid barrier (no atomic serialization) --------
__device__ __forceinline__ void gsync(unsigned idx) {
    __threadfence();            // release: every thread fences its own writes
    __syncthreads();
    if (threadIdx.x == 0) g_flags[blockIdx.x] = idx;
    if (threadIdx.x < GRID_G) {
        while (g_flags[threadIdx.x] < idx) { }
    }
    __threadfence();            // acquire: invalidate L1 before consuming
    __syncthreads();
}

// ================= Kernel 1: xin = emb[x] @ Wx + b  (fp32x2) =================
__global__ void xin_kernel(const int* __restrict__ x, const float* __restrict__ emb,
                           const float* __restrict__ w1, const float* __restrict__ b1) {
    __shared__ __align__(16) float2 Asd[64*16];  // duplicated A: Asd[row][kk]=(v,v)
    __shared__ __align__(16) float  Bs[16*64];   // Bs[kk][n]
    __shared__ int rows[64];
    const int tid = threadIdx.x;
    const int n0 = blockIdx.x * 64;
    const int r0 = blockIdx.y * 64;
    const int tx = tid & 15, ty = tid >> 4;

    if (tid < 64) rows[tid] = x[r0 + tid];
    __syncthreads();

    ull acc[4][2] = {};
    for (int k0 = 0; k0 < H_; k0 += 16) {
        #pragma unroll
        for (int j = 0; j < 4; j++) {
            int f = tid + j * 256;
            int row = f >> 4, kk = f & 15;
            float v = emb[rows[row] * H_ + k0 + kk];
            Asd[row * 16 + kk] = make_float2(v, v);
            int bkk = f >> 6, bn = f & 63;
            Bs[bkk * 64 + bn] = w1[(k0 + bkk) * SIXH + n0 + bn];
        }
        __syncthreads();
        #pragma unroll
        for (int kk = 0; kk < 16; kk++) {
            ull a0 = *(const ull*)&Asd[(ty*4+0)*16 + kk];
            ull a1 = *(const ull*)&Asd[(ty*4+1)*16 + kk];
            ull a2 = *(const ull*)&Asd[(ty*4+2)*16 + kk];
            ull a3 = *(const ull*)&Asd[(ty*4+3)*16 + kk];
            ulonglong2 bp = *(const ulonglong2*)&Bs[kk*64 + tx*4];
            acc[0][0] = fma2(a0, bp.x, acc[0][0]); acc[0][1] = fma2(a0, bp.y, acc[0][1]);
            acc[1][0] = fma2(a1, bp.x, acc[1][0]); acc[1][1] = fma2(a1, bp.y, acc[1][1]);
            acc[2][0] = fma2(a2, bp.x, acc[2][0]); acc[2][1] = fma2(a2, bp.y, acc[2][1]);
            acc[3][0] = fma2(a3, bp.x, acc[3][0]); acc[3][1] = fma2(a3, bp.y, acc[3][1]);
        }
        __syncthreads();
    }
    float4 bb = *(const float4*)&b1[n0 + tx*4];
    #pragma unroll
    for (int i = 0; i < 4; i++) {
        float2 p0 = *(float2*)&acc[i][0];
        float2 p1 = *(float2*)&acc[i][1];
        float4 o = make_float4(p0.x + bb.x, p0.y + bb.y, p1.x + bb.z, p1.y + bb.w);
        *(float4*)&g_xin[(r0 + ty*4 + i) * H_ + n0 + tx*4] = o;
    }
}

// ================= Kernel 2: persistent recurrence (fp32x2) =================
// 128 CTAs: nt = bx>>3 (64-col N tile), ks = bx&7 (128-row K slice).
// Dyn SMEM: hsd[64][128] duplicated h slice (64KB) + Whs[128][64] (32KB).
__global__ void recur_kernel(const float* __restrict__ w1, float* __restrict__ out_hist) {
    extern __shared__ __align__(16) char smem_raw[];
    float2* hsd = (float2*)smem_raw;                  // hsd[b*128 + kk] = (v,v)
    float*  Whs = (float*)(smem_raw + 64*128*8);      // Whs[kk*64 + nn]

    const int tid = threadIdx.x;
    const int bx  = blockIdx.x;
    const int nt = bx >> 3, ks = bx & 7;
    const int tx = tid & 15, ty = tid >> 4;

    unsigned idx = g_epoch;   // base epoch from previous launch (stream-ordered)

    // Load resident Wh slab: Wh[k][n] = w1[k*6144 + 1024 + n]
    for (int f = tid; f < 128*64; f += 256) {
        int kk = f >> 6, nn = f & 63;
        Whs[f] = w1[(ks*128 + kk) * SIXH + H_ + nt*64 + nn];
    }

    // Prologue: h0 = tanh(xin[0])
    #pragma unroll
    for (int i = 0; i < 2; i++) {
        int e = bx * 512 + i * 256 + tid;
        float v = tanhf(g_xin[e]);
        g_h[e] = v;
        out_hist[(e >> 10) * (T_*H_) + (e & 1023)] = v;   // t = 0
    }
    gsync(++idx);

    // initial hsd load
    #pragma unroll
    for (int i = 0; i < 8; i++) {
        int f = tid + i * 256;                 // f < 2048 float4 groups
        int b = f >> 5, kk4 = f & 31;
        float4 v = __ldcg((const float4*)&g_h[b * H_ + ks*128 + kk4*4]);
        float2* d = &hsd[b*128 + kk4*4];
        *(float4*)(d)     = make_float4(v.x, v.x, v.y, v.y);
        *(float4*)(d + 2) = make_float4(v.z, v.z, v.w, v.w);
    }
    __syncthreads();

    for (int t = 1; t < T_; t++) {
        for (int j = 0; j < 2; j++) {
            // ---- GEMM: part[ks][b][nt cols] = h[:,ks slice] @ Wh slab ----
            ull acc[4][2] = {};
            const float2* hr0 = hsd + (ty*4+0)*128;
            const float2* hr1 = hsd + (ty*4+1)*128;
            const float2* hr2 = hsd + (ty*4+2)*128;
            const float2* hr3 = hsd + (ty*4+3)*128;
            #pragma unroll 16
            for (int kk = 0; kk < 128; kk++) {
                ull a0 = *(const ull*)(hr0 + kk);
                ull a1 = *(const ull*)(hr1 + kk);
                ull a2 = *(const ull*)(hr2 + kk);
                ull a3 = *(const ull*)(hr3 + kk);
                ulonglong2 bp = *(const ulonglong2*)&Whs[kk*64 + tx*4];
                acc[0][0] = fma2(a0, bp.x, acc[0][0]); acc[0][1] = fma2(a0, bp.y, acc[0][1]);
                acc[1][0] = fma2(a1, bp.x, acc[1][0]); acc[1][1] = fma2(a1, bp.y, acc[1][1]);
                acc[2][0] = fma2(a2, bp.x, acc[2][0]); acc[2][1] = fma2(a2, bp.y, acc[2][1]);
                acc[3][0] = fma2(a3, bp.x, acc[3][0]); acc[3][1] = fma2(a3, bp.y, acc[3][1]);
            }
            #pragma unroll
            for (int i = 0; i < 4; i++) {
                float2 p0 = *(float2*)&acc[i][0];
                float2 p1 = *(float2*)&acc[i][1];
                *(float4*)&g_part[ks*BH + (ty*4+i)*H_ + nt*64 + tx*4] =
                    make_float4(p0.x, p0.y, p1.x, p1.y);
            }
            // prefetch xin for reduce (independent of barrier)
            float x0 = __ldcg(&g_xin[t*BH + bx*512 + tid]);
            float x1 = __ldcg(&g_xin[t*BH + bx*512 + 256 + tid]);
            gsync(++idx);

            // ---- reduce + tanh on own 512-elem chunk ----
            const bool wr = (j == 1);
            #pragma unroll
            for (int i = 0; i < 2; i++) {
                int e = bx * 512 + i * 256 + tid;
                float s = (i == 0) ? x0 : x1;
                #pragma unroll
                for (int p = 0; p < 8; p++) s += __ldcg(&g_part[p*BH + e]);
                float v = tanhf(s);
                g_h[e] = v;
                if (wr) out_hist[(e >> 10) * (T_*H_) + t * H_ + (e & 1023)] = v;
            }
            if (t == T_-1 && j == 1) break;   // last: fc kernel reads g_h (kernel boundary orders)
            gsync(++idx);

            // reload hsd from new h
            #pragma unroll
            for (int i = 0; i < 8; i++) {
                int f = tid + i * 256;
                int b = f >> 5, kk4 = f & 31;
                float4 v = __ldcg((const float4*)&g_h[b * H_ + ks*128 + kk4*4]);
                float2* d = &hsd[b*128 + kk4*4];
                *(float4*)(d)     = make_float4(v.x, v.x, v.y, v.y);
                *(float4*)(d + 2) = make_float4(v.z, v.z, v.w, v.w);
            }
            __syncthreads();
        }
    }
    // advance epoch for next graph replay (others may still be polling flags; they
    // never read g_epoch after start, so this is safe)
    if (bx == 0 && tid == 0) g_epoch = idx;
}

// ================= Kernel 3: y = h_last @ fc_w^T + fc_b =================
__global__ void fc_kernel(const float* __restrict__ fc_w, const float* __restrict__ fc_b,
                          float* __restrict__ y) {
    __shared__ __align__(16) float As[64*16];
    __shared__ __align__(16) float Bs[16*64];
    const int tid = threadIdx.x;
    const int c0 = blockIdx.x * 64;
    const int tx = tid & 15, ty = tid >> 4;

    float acc[4][4] = {};
    for (int k0 = 0; k0 < H_; k0 += 16) {
        #pragma unroll
        for (int j = 0; j < 4; j++) {
            int f = tid + j * 256;
            int row = f >> 4, kk = f & 15;
            As[row * 16 + kk] = g_h[row * H_ + k0 + kk];
            Bs[kk * 64 + row] = fc_w[(c0 + row) * H_ + k0 + kk];
        }
        __syncthreads();
        #pragma unroll
        for (int kk = 0; kk < 16; kk++) {
            float a0 = As[(ty*4+0)*16 + kk];
            float a1 = As[(ty*4+1)*16 + kk];
            float a2 = As[(ty*4+2)*16 + kk];
            float a3 = As[(ty*4+3)*16 + kk];
            float4 bv = *(const float4*)&Bs[kk*64 + tx*4];
            acc[0][0] += a0*bv.x; acc[0][1] += a0*bv.y; acc[0][2] += a0*bv.z; acc[0][3] += a0*bv.w;
            acc[1][0] += a1*bv.x; acc[1][1] += a1*bv.y; acc[1][2] += a1*bv.z; acc[1][3] += a1*bv.w;
            acc[2][0] += a2*bv.x; acc[2][1] += a2*bv.y; acc[2][2] += a2*bv.z; acc[2][3] += a2*bv.w;
            acc[3][0] += a3*bv.x; acc[3][1] += a3*bv.y; acc[3][2] += a3*bv.z; acc[3][3] += a3*bv.w;
        }
        __syncthreads();
    }
    #pragma unroll
    for (int i = 0; i < 4; i++) {
        #pragma unroll
        for (int j = 0; j < 4; j++) {
            int c = c0 + tx*4 + j;
            y[(ty*4 + i) * C_ + c] = acc[i][j] + fc_b[c];
        }
    }
}

// ================= launch =================
extern "C" void kernel_launch(void* const* d_in, const int* in_sizes, int n_in,
                              void* d_out, int out_size) {
    const int*   x    = (const int*)  d_in[0];
    const float* emb  = (const float*)d_in[1];
    const float* w1   = (const float*)d_in[2];
    const float* b1   = (const float*)d_in[3];
    const float* fc_w = (const float*)d_in[4];
    const float* fc_b = (const float*)d_in[5];
    float* out = (float*)d_out;

    dim3 g1(H_/64, M_/64);
    xin_kernel<<<g1, 256>>>(x, emb, w1, b1);

    const int smem = 64*128*8 + 128*64*4;   // 96 KB
    cudaFuncSetAttribute(recur_kernel, cudaFuncAttributeMaxDynamicSharedMemorySize, smem);
    recur_kernel<<<GRID_G, 256, smem>>>(w1, out + YSIZE);

    fc_kernel<<<C_/64, 256>>>(fc_w, fc_b, out);
}

// round 4
// speedup vs baseline: 2.5062x; 2.5062x over previous
#include <cuda_runtime.h>
#include <math.h>

// Problem constants
#define T_    512
#define B_    64
#define H_    1024
#define C_    32000
#define SIXH  6144
#define M_    (T_*B_)        // 32768 rows of xin
#define BH    (B_*H_)        // 65536
#define YSIZE (B_*C_)
#define GRID_G 128           // persistent kernel CTAs (<=148 SMs => co-resident)

// -------- scratch (no cudaMalloc allowed) --------
__device__ float    g_xin[M_*H_];       // xin[t*64+b][n]
__device__ float    g_h[BH];            // current hidden state
__device__ float    g_part[8*BH];       // K-split partial sums: part[ks][b][n]
__device__ unsigned g_bar   = 0;        // monotonic barrier counter (REDG target)
__device__ unsigned g_epoch = 0;        // barrier-count base, advanced once per launch

// -------- grid barrier: REDG arrival (no atomic serialization) + acquire poll --------
__device__ __forceinline__ void gsync(unsigned idx) {
    __syncthreads();                          // CTA-scope fence: all threads' writes visible to tid0
    if (threadIdx.x == 0) {
        // release-arrive: cumulative release publishes this CTA's prior writes
        asm volatile("red.release.gpu.global.add.u32 [%0], %1;"
                     :: "l"(&g_bar), "r"(1u) : "memory");
        const unsigned target = idx * GRID_G;
        unsigned v;
        do {
            asm volatile("ld.acquire.gpu.global.u32 %0, [%1];"
                         : "=r"(v) : "l"(&g_bar) : "memory");
        } while (v < target);
    }
    __syncthreads();
}

// ================= Kernel 1: xin = emb[x] @ Wx + b =================
// 128x64 CTA tile, 256 threads, 8x4 per thread, K-tile 16, As stored k-major.
__global__ void xin_kernel(const int* __restrict__ x, const float* __restrict__ emb,
                           const float* __restrict__ w1, const float* __restrict__ b1) {
    __shared__ __align__(16) float As[16*128];  // As[kk][row]  (k-major!)
    __shared__ __align__(16) float Bs[16*64];   // Bs[kk][n]
    __shared__ int rows[128];
    const int tid = threadIdx.x;
    const int n0 = blockIdx.x * 64;
    const int r0 = blockIdx.y * 128;
    const int tx = tid & 15, ty = tid >> 4;

    if (tid < 128) rows[tid] = x[r0 + tid];
    __syncthreads();

    float acc[8][4] = {};
    for (int k0 = 0; k0 < H_; k0 += 16) {
        // load As: 128 rows x 16 kk = 512 float4 (2 per thread), store transposed
        #pragma unroll
        for (int j = 0; j < 2; j++) {
            int f = tid + j * 256;              // f in [0,512)
            int row = f >> 2, kk4 = f & 3;
            float4 v = *(const float4*)&emb[rows[row] * H_ + k0 + kk4 * 4];
            As[(kk4*4 + 0) * 128 + row] = v.x;
            As[(kk4*4 + 1) * 128 + row] = v.y;
            As[(kk4*4 + 2) * 128 + row] = v.z;
            As[(kk4*4 + 3) * 128 + row] = v.w;
        }
        // load Bs: 16 x 64 = 256 float4 (1 per thread)
        {
            int bkk = tid >> 4, bn4 = tid & 15;
            *(float4*)&Bs[bkk * 64 + bn4 * 4] =
                *(const float4*)&w1[(k0 + bkk) * SIXH + n0 + bn4 * 4];
        }
        __syncthreads();
        #pragma unroll
        for (int kk = 0; kk < 16; kk++) {
            float4 a03 = *(const float4*)&As[kk*128 + ty*8];
            float4 a47 = *(const float4*)&As[kk*128 + ty*8 + 4];
            float4 bv  = *(const float4*)&Bs[kk*64 + tx*4];
            float a[8] = {a03.x, a03.y, a03.z, a03.w, a47.x, a47.y, a47.z, a47.w};
            #pragma unroll
            for (int i = 0; i < 8; i++) {
                acc[i][0] += a[i]*bv.x; acc[i][1] += a[i]*bv.y;
                acc[i][2] += a[i]*bv.z; acc[i][3] += a[i]*bv.w;
            }
        }
        __syncthreads();
    }
    float4 bb = *(const float4*)&b1[n0 + tx*4];
    #pragma unroll
    for (int i = 0; i < 8; i++) {
        float4 o = make_float4(acc[i][0] + bb.x, acc[i][1] + bb.y,
                               acc[i][2] + bb.z, acc[i][3] + bb.w);
        *(float4*)&g_xin[(r0 + ty*8 + i) * H_ + n0 + tx*4] = o;
    }
}

// ================= Kernel 2: persistent recurrence =================
// 128 CTAs: nt = bx>>3 (64-col N tile), ks = bx&7 (128-row K slice).
// Dyn SMEM: hs[64][128] (32KB) + Whs[128][64] (32KB). Wh slab resident.
__global__ void recur_kernel(const float* __restrict__ w1, float* __restrict__ out_hist) {
    extern __shared__ __align__(16) char smem_raw[];
    float* hs  = (float*)smem_raw;                 // hs[b*128 + kk]
    float* Whs = (float*)(smem_raw + 64*128*4);    // Whs[kk*64 + nn]

    const int tid = threadIdx.x;
    const int bx  = blockIdx.x;
    const int nt = bx >> 3, ks = bx & 7;
    const int tx = tid & 15, ty = tid >> 4;

    unsigned idx = __ldcg(&g_epoch);   // base barrier count (stream-ordered from prev launch)

    // Load resident Wh slab: Wh[k][n] = w1[k*6144 + 1024 + n]
    for (int f = tid; f < 128*64; f += 256) {
        int kk = f >> 6, nn = f & 63;
        Whs[f] = w1[(ks*128 + kk) * SIXH + H_ + nt*64 + nn];
    }

    // Prologue: h0 = tanh(xin[0])
    #pragma unroll
    for (int i = 0; i < 2; i++) {
        int e = bx * 512 + i * 256 + tid;
        float v = tanhf(g_xin[e]);
        g_h[e] = v;
        out_hist[(e >> 10) * (T_*H_) + (e & 1023)] = v;   // t = 0
    }
    gsync(++idx);

    // initial hs load: h[all 64 b][ks*128 .. +128)
    #pragma unroll
    for (int i = 0; i < 8; i++) {
        int f = tid + i * 256;                 // f < 2048 float4 groups
        int b = f >> 5, kk4 = f & 31;
        float4 v = __ldcg((const float4*)&g_h[b * H_ + ks*128 + kk4*4]);
        *(float4*)&hs[b*128 + kk4*4] = v;
    }
    __syncthreads();

    for (int t = 1; t < T_; t++) {
        for (int j = 0; j < 2; j++) {
            // ---- GEMM: part[ks][b][nt cols] = h[:,ks slice] @ Wh slab ----
            float acc[4][4] = {};
            const float* hr0 = hs + (ty*4+0)*128;
            const float* hr1 = hs + (ty*4+1)*128;
            const float* hr2 = hs + (ty*4+2)*128;
            const float* hr3 = hs + (ty*4+3)*128;
            #pragma unroll 8
            for (int kk = 0; kk < 128; kk++) {
                float a0 = hr0[kk], a1 = hr1[kk], a2 = hr2[kk], a3 = hr3[kk];
                float4 bv = *(const float4*)&Whs[kk*64 + tx*4];
                acc[0][0] += a0*bv.x; acc[0][1] += a0*bv.y; acc[0][2] += a0*bv.z; acc[0][3] += a0*bv.w;
                acc[1][0] += a1*bv.x; acc[1][1] += a1*bv.y; acc[1][2] += a1*bv.z; acc[1][3] += a1*bv.w;
                acc[2][0] += a2*bv.x; acc[2][1] += a2*bv.y; acc[2][2] += a2*bv.z; acc[2][3] += a2*bv.w;
                acc[3][0] += a3*bv.x; acc[3][1] += a3*bv.y; acc[3][2] += a3*bv.z; acc[3][3] += a3*bv.w;
            }
            #pragma unroll
            for (int i = 0; i < 4; i++) {
                *(float4*)&g_part[ks*BH + (ty*4+i)*H_ + nt*64 + tx*4] =
                    make_float4(acc[i][0], acc[i][1], acc[i][2], acc[i][3]);
            }
            // prefetch xin for reduce (independent of barrier)
            float2 xp = __ldcg((const float2*)&g_xin[t*BH + bx*512] + tid);
            gsync(++idx);

            // ---- reduce + tanh on own 512-elem chunk (256 float2/thread-block) ----
            const bool wr = (j == 1);
            {
                float2 s = xp;
                #pragma unroll
                for (int p = 0; p < 8; p++) {
                    float2 pv = __ldcg((const float2*)&g_part[p*BH + bx*512] + tid);
                    s.x += pv.x; s.y += pv.y;
                }
                float2 v = make_float2(tanhf(s.x), tanhf(s.y));
                int e = bx * 512 + tid * 2;
                *(float2*)&g_h[e] = v;
                if (wr) *(float2*)&out_hist[(e >> 10) * (T_*H_) + t * H_ + (e & 1023)] = v;
            }
            if (t == T_-1 && j == 1) break;   // fc kernel reads g_h across launch boundary
            gsync(++idx);

            // reload hs from new h
            #pragma unroll
            for (int i = 0; i < 8; i++) {
                int f = tid + i * 256;
                int b = f >> 5, kk4 = f & 31;
                float4 v = __ldcg((const float4*)&g_h[b * H_ + ks*128 + kk4*4]);
                *(float4*)&hs[b*128 + kk4*4] = v;
            }
            __syncthreads();
        }
    }
    // advance epoch base for next graph replay
    if (bx == 0 && tid == 0) g_epoch = idx;
}

// ================= Kernel 3: y = h_last @ fc_w^T + fc_b =================
__global__ void fc_kernel(const float* __restrict__ fc_w, const float* __restrict__ fc_b,
                          float* __restrict__ y) {
    __shared__ __align__(16) float As[64*16];
    __shared__ __align__(16) float Bs[16*64];
    const int tid = threadIdx.x;
    const int c0 = blockIdx.x * 64;
    const int tx = tid & 15, ty = tid >> 4;

    float acc[4][4] = {};
    for (int k0 = 0; k0 < H_; k0 += 16) {
        #pragma unroll
        for (int j = 0; j < 4; j++) {
            int f = tid + j * 256;
            int row = f >> 4, kk = f & 15;
            As[row * 16 + kk] = g_h[row * H_ + k0 + kk];
            Bs[kk * 64 + row] = fc_w[(c0 + row) * H_ + k0 + kk];
        }
        __syncthreads();
        #pragma unroll
        for (int kk = 0; kk < 16; kk++) {
            float a0 = As[(ty*4+0)*16 + kk];
            float a1 = As[(ty*4+1)*16 + kk];
            float a2 = As[(ty*4+2)*16 + kk];
            float a3 = As[(ty*4+3)*16 + kk];
            float4 bv = *(const float4*)&Bs[kk*64 + tx*4];
            acc[0][0] += a0*bv.x; acc[0][1] += a0*bv.y; acc[0][2] += a0*bv.z; acc[0][3] += a0*bv.w;
            acc[1][0] += a1*bv.x; acc[1][1] += a1*bv.y; acc[1][2] += a1*bv.z; acc[1][3] += a1*bv.w;
            acc[2][0] += a2*bv.x; acc[2][1] += a2*bv.y; acc[2][2] += a2*bv.z; acc[2][3] += a2*bv.w;
            acc[3][0] += a3*bv.x; acc[3][1] += a3*bv.y; acc[3][2] += a3*bv.z; acc[3][3] += a3*bv.w;
        }
        __syncthreads();
    }
    #pragma unroll
    for (int i = 0; i < 4; i++) {
        #pragma unroll
        for (int j = 0; j < 4; j++) {
            int c = c0 + tx*4 + j;
            y[(ty*4 + i) * C_ + c] = acc[i][j] + fc_b[c];
        }
    }
}

// ================= launch =================
extern "C" void kernel_launch(void* const* d_in, const int* in_sizes, int n_in,
                              void* d_out, int out_size) {
    const int*   x    = (const int*)  d_in[0];
    const float* emb  = (const float*)d_in[1];
    const float* w1   = (const float*)d_in[2];
    const float* b1   = (const float*)d_in[3];
    const float* fc_w = (const float*)d_in[4];
    const float* fc_b = (const float*)d_in[5];
    float* out = (float*)d_out;

    dim3 g1(H_/64, M_/128);
    xin_kernel<<<g1, 256>>>(x, emb, w1, b1);

    const int smem = 64*128*4 + 128*64*4;   // 64 KB dynamic
    cudaFuncSetAttribute(recur_kernel, cudaFuncAttributeMaxDynamicSharedMemorySize, smem);
    recur_kernel<<<GRID_G, 256, smem>>>(w1, out + YSIZE);

    fc_kernel<<<C_/64, 256>>>(fc_w, fc_b, out);
}

// round 6
// speedup vs baseline: 3.0613x; 1.2215x over previous
#include <cuda_runtime.h>
#include <cuda_bf16.h>
#include <math.h>
#include <stdint.h>

// Problem constants
#define T_    512
#define B_    64
#define H_    1024
#define C_    32000
#define SIXH  6144
#define M_    (T_*B_)
#define BH    (B_*H_)
#define YSIZE (B_*C_)
#define GRID_G 128

// -------- scratch --------
__device__ float    g_xin[M_*H_];
__device__ float    g_h[BH];
__device__ float    g_part[8*BH];
__device__ unsigned g_bar   = 0;
__device__ unsigned g_epoch = 0;

// -------- grid barrier: REDG arrival + acquire poll (round-4 proven) --------
__device__ __forceinline__ void gsync(unsigned idx) {
    __syncthreads();
    if (threadIdx.x == 0) {
        asm volatile("red.release.gpu.global.add.u32 [%0], %1;"
                     :: "l"(&g_bar), "r"(1u) : "memory");
        const unsigned target = idx * GRID_G;
        unsigned v;
        do {
            asm volatile("ld.acquire.gpu.global.u32 %0, [%1];"
                         : "=r"(v) : "l"(&g_bar) : "memory");
        } while (v < target);
    }
    __syncthreads();
}

__device__ __forceinline__ uint32_t smem_u32(const void* p) {
    uint32_t a;
    asm("{ .reg .u64 t; cvta.to.shared.u64 t, %1; cvt.u32.u64 %0, t; }" : "=r"(a) : "l"(p));
    return a;
}
__device__ __forceinline__ void ldsm4(uint32_t* r, uint32_t a) {
    asm volatile("ldmatrix.sync.aligned.m8n8.x4.shared.b16 {%0,%1,%2,%3}, [%4];"
        : "=r"(r[0]), "=r"(r[1]), "=r"(r[2]), "=r"(r[3]) : "r"(a));
}
__device__ __forceinline__ void ldsm2(uint32_t* r, uint32_t a) {
    asm volatile("ldmatrix.sync.aligned.m8n8.x2.shared.b16 {%0,%1}, [%2];"
        : "=r"(r[0]), "=r"(r[1]) : "r"(a));
}
__device__ __forceinline__ void mma_bf16(float* d, const uint32_t* a, const uint32_t* b) {
    asm volatile("mma.sync.aligned.m16n8k16.row.col.f32.bf16.bf16.f32 "
        "{%0,%1,%2,%3}, {%4,%5,%6,%7}, {%8,%9}, {%0,%1,%2,%3};"
        : "+f"(d[0]), "+f"(d[1]), "+f"(d[2]), "+f"(d[3])
        : "r"(a[0]), "r"(a[1]), "r"(a[2]), "r"(a[3]), "r"(b[0]), "r"(b[1]));
}

// smem layout: 272-byte row stride (68 words: 8 ldmatrix rows tile 32 banks, conflict-free)
#define RSTR   272
#define S_AHI  0
#define S_ALO  (64*RSTR)
#define S_BHI  (2*64*RSTR)
#define S_BLO  (3*64*RSTR)
#define S_TOTAL (4*64*RSTR)    // 69632 B

// ================= Kernel 1: xin = emb[x] @ Wx + b (round-4, unchanged) ==========
__global__ void xin_kernel(const int* __restrict__ x, const float* __restrict__ emb,
                           const float* __restrict__ w1, const float* __restrict__ b1) {
    __shared__ __align__(16) float As[16*128];
    __shared__ __align__(16) float Bs[16*64];
    __shared__ int rows[128];
    const int tid = threadIdx.x;
    const int n0 = blockIdx.x * 64;
    const int r0 = blockIdx.y * 128;
    const int tx = tid & 15, ty = tid >> 4;

    if (tid < 128) rows[tid] = x[r0 + tid];
    __syncthreads();

    float acc[8][4] = {};
    for (int k0 = 0; k0 < H_; k0 += 16) {
        #pragma unroll
        for (int j = 0; j < 2; j++) {
            int f = tid + j * 256;
            int row = f >> 2, kk4 = f & 3;
            float4 v = *(const float4*)&emb[rows[row] * H_ + k0 + kk4 * 4];
            As[(kk4*4 + 0) * 128 + row] = v.x;
            As[(kk4*4 + 1) * 128 + row] = v.y;
            As[(kk4*4 + 2) * 128 + row] = v.z;
            As[(kk4*4 + 3) * 128 + row] = v.w;
        }
        {
            int bkk = tid >> 4, bn4 = tid & 15;
            *(float4*)&Bs[bkk * 64 + bn4 * 4] =
                *(const float4*)&w1[(k0 + bkk) * SIXH + n0 + bn4 * 4];
        }
        __syncthreads();
        #pragma unroll
        for (int kk = 0; kk < 16; kk++) {
            float4 a03 = *(const float4*)&As[kk*128 + ty*8];
            float4 a47 = *(const float4*)&As[kk*128 + ty*8 + 4];
            float4 bv  = *(const float4*)&Bs[kk*64 + tx*4];
            float a[8] = {a03.x, a03.y, a03.z, a03.w, a47.x, a47.y, a47.z, a47.w};
            #pragma unroll
            for (int i = 0; i < 8; i++) {
                acc[i][0] += a[i]*bv.x; acc[i][1] += a[i]*bv.y;
                acc[i][2] += a[i]*bv.z; acc[i][3] += a[i]*bv.w;
            }
        }
        __syncthreads();
    }
    float4 bb = *(const float4*)&b1[n0 + tx*4];
    #pragma unroll
    for (int i = 0; i < 8; i++) {
        float4 o = make_float4(acc[i][0] + bb.x, acc[i][1] + bb.y,
                               acc[i][2] + bb.z, acc[i][3] + bb.w);
        *(float4*)&g_xin[(r0 + ty*8 + i) * H_ + n0 + tx*4] = o;
    }
}

// ================= Kernel 2: persistent recurrence (mma.sync bf16 3-split) ==========
// 128 CTAs: nt = bx>>3 (64 N cols), ks = bx&7 (128 K rows).
// Per inner step: part[64,64] = Ahi@Bhi + Ahi@Blo + Alo@Bhi (fp32 HMMA accum).
__global__ void __launch_bounds__(256, 1)
recur_kernel(const float* __restrict__ w1, float* __restrict__ out_hist) {
    extern __shared__ __align__(1024) char smem[];
    const uint32_t sb = smem_u32(smem);
    const int tid = threadIdx.x;
    const int wid = tid >> 5;
    const int l   = tid & 31;
    const int bx  = blockIdx.x;
    const int nt = bx >> 3, ks = bx & 7;
    const int m  = wid & 3;        // M-tile (16 rows)
    const int nh = wid >> 2;       // N-half (32 cols)

    unsigned idx = __ldcg(&g_epoch);

    // ---- one-time: Wh slab -> Bhi/Blo[n][k] bf16, 272B row stride ----
    #pragma unroll
    for (int it = 0; it < 8; it++) {
        int f = tid + it * 256;               // 2048 tasks: 128 k x 16 n-quads
        int k = f >> 4, nq = (f & 15) * 4;
        float4 v = *(const float4*)&w1[(ks*128 + k) * SIXH + H_ + nt*64 + nq];
        float vv[4] = {v.x, v.y, v.z, v.w};
        #pragma unroll
        for (int q = 0; q < 4; q++) {
            int off = (nq + q) * RSTR + k * 2;
            __nv_bfloat16 hi = __float2bfloat16(vv[q]);
            __nv_bfloat16 lo = __float2bfloat16(vv[q] - __bfloat162float(hi));
            *(__nv_bfloat16*)(smem + S_BHI + off) = hi;
            *(__nv_bfloat16*)(smem + S_BLO + off) = lo;
        }
    }

    // ---- prologue: h0 = tanh(xin[0]) ----
    #pragma unroll
    for (int i = 0; i < 2; i++) {
        int e = bx * 512 + i * 256 + tid;
        float v = tanhf(g_xin[e]);
        g_h[e] = v;
        out_hist[(e >> 10) * (T_*H_) + (e & 1023)] = v;   // t = 0
    }
    gsync(++idx);

    // ldmatrix address bases (constant across iterations)
    const uint32_t a_addr0 = sb + (uint32_t)((m*16 + (l & 7) + ((l >> 3) & 1) * 8) * RSTR
                                             + ((l >> 4) & 1) * 16);
    const uint32_t b_addr0 = sb + (uint32_t)((nh*32 + (l & 7)) * RSTR + ((l >> 3) & 1) * 16);

    // ---- convert h slice -> Ahi/Alo bf16 [b][k], 272B stride ----
    auto convert_h = [&]() {
        int b = tid >> 2, c0 = (tid & 3) * 32;
        #pragma unroll
        for (int i = 0; i < 8; i++) {
            int c = c0 + i * 4;
            float4 v = __ldcg((const float4*)&g_h[b * H_ + ks*128 + c]);
            int off = b * RSTR + c * 2;
            __nv_bfloat16 hx = __float2bfloat16(v.x), hy = __float2bfloat16(v.y);
            __nv_bfloat16 hz = __float2bfloat16(v.z), hw = __float2bfloat16(v.w);
            *(__nv_bfloat162*)(smem + S_AHI + off)     = __halves2bfloat162(hx, hy);
            *(__nv_bfloat162*)(smem + S_AHI + off + 4) = __halves2bfloat162(hz, hw);
            __nv_bfloat16 lx = __float2bfloat16(v.x - __bfloat162float(hx));
            __nv_bfloat16 ly = __float2bfloat16(v.y - __bfloat162float(hy));
            __nv_bfloat16 lz = __float2bfloat16(v.z - __bfloat162float(hz));
            __nv_bfloat16 lw = __float2bfloat16(v.w - __bfloat162float(hw));
            *(__nv_bfloat162*)(smem + S_ALO + off)     = __halves2bfloat162(lx, ly);
            *(__nv_bfloat162*)(smem + S_ALO + off + 4) = __halves2bfloat162(lz, lw);
        }
    };
    convert_h();
    __syncthreads();

    for (int t = 1; t < T_; t++) {
        for (int j = 0; j < 2; j++) {
            // ---- GEMM: 16x32 per warp, K=128 in 8 steps, 3 bf16 products ----
            float d[4][4] = {};
            #pragma unroll
            for (int s = 0; s < 8; s++) {
                uint32_t a_hi[4], a_lo[4];
                ldsm4(a_hi, a_addr0 + S_AHI + s * 32);
                ldsm4(a_lo, a_addr0 + S_ALO + s * 32);
                #pragma unroll
                for (int ns = 0; ns < 4; ns++) {
                    uint32_t b_hi[2], b_lo[2];
                    uint32_t bo = b_addr0 + (uint32_t)(ns * 8 * RSTR) + s * 32;
                    ldsm2(b_hi, bo + S_BHI);
                    ldsm2(b_lo, bo + S_BLO);
                    mma_bf16(d[ns], a_hi, b_hi);
                    mma_bf16(d[ns], a_hi, b_lo);
                    mma_bf16(d[ns], a_lo, b_hi);
                }
            }
            // epilogue: write partial tile
            {
                int row0 = m*16 + (l >> 2);
                int gcol = nt*64 + nh*32 + (l & 3) * 2;
                float* p = &g_part[ks*BH + row0*H_ + gcol];
                #pragma unroll
                for (int ns = 0; ns < 4; ns++) {
                    *(float2*)(p + ns*8)          = make_float2(d[ns][0], d[ns][1]);
                    *(float2*)(p + ns*8 + 8*H_)   = make_float2(d[ns][2], d[ns][3]);
                }
            }
            float2 xp = __ldcg((const float2*)&g_xin[t*BH + bx*512] + tid);
            gsync(++idx);

            // ---- reduce + tanh on own 512-elem chunk ----
            const bool wr = (j == 1);
            {
                float2 s = xp;
                #pragma unroll
                for (int p = 0; p < 8; p++) {
                    float2 pv = __ldcg((const float2*)&g_part[p*BH + bx*512] + tid);
                    s.x += pv.x; s.y += pv.y;
                }
                float2 v = make_float2(tanhf(s.x), tanhf(s.y));
                int e = bx * 512 + tid * 2;
                *(float2*)&g_h[e] = v;
                if (wr) *(float2*)&out_hist[(e >> 10) * (T_*H_) + t * H_ + (e & 1023)] = v;
            }
            if (t == T_-1 && j == 1) break;
            gsync(++idx);

            convert_h();
            __syncthreads();
        }
    }
    if (bx == 0 && tid == 0) g_epoch = idx;
}

// ================= Kernel 3: y = h_last @ fc_w^T + fc_b (unchanged) ==========
__global__ void fc_kernel(const float* __restrict__ fc_w, const float* __restrict__ fc_b,
                          float* __restrict__ y) {
    __shared__ __align__(16) float As[64*16];
    __shared__ __align__(16) float Bs[16*64];
    const int tid = threadIdx.x;
    const int c0 = blockIdx.x * 64;
    const int tx = tid & 15, ty = tid >> 4;

    float acc[4][4] = {};
    for (int k0 = 0; k0 < H_; k0 += 16) {
        #pragma unroll
        for (int j = 0; j < 4; j++) {
            int f = tid + j * 256;
            int row = f >> 4, kk = f & 15;
            As[row * 16 + kk] = g_h[row * H_ + k0 + kk];
            Bs[kk * 64 + row] = fc_w[(c0 + row) * H_ + k0 + kk];
        }
        __syncthreads();
        #pragma unroll
        for (int kk = 0; kk < 16; kk++) {
            float a0 = As[(ty*4+0)*16 + kk];
            float a1 = As[(ty*4+1)*16 + kk];
            float a2 = As[(ty*4+2)*16 + kk];
            float a3 = As[(ty*4+3)*16 + kk];
            float4 bv = *(const float4*)&Bs[kk*64 + tx*4];
            acc[0][0] += a0*bv.x; acc[0][1] += a0*bv.y; acc[0][2] += a0*bv.z; acc[0][3] += a0*bv.w;
            acc[1][0] += a1*bv.x; acc[1][1] += a1*bv.y; acc[1][2] += a1*bv.z; acc[1][3] += a1*bv.w;
            acc[2][0] += a2*bv.x; acc[2][1] += a2*bv.y; acc[2][2] += a2*bv.z; acc[2][3] += a2*bv.w;
            acc[3][0] += a3*bv.x; acc[3][1] += a3*bv.y; acc[3][2] += a3*bv.z; acc[3][3] += a3*bv.w;
        }
        __syncthreads();
    }
    #pragma unroll
    for (int i = 0; i < 4; i++) {
        #pragma unroll
        for (int j = 0; j < 4; j++) {
            int c = c0 + tx*4 + j;
            y[(ty*4 + i) * C_ + c] = acc[i][j] + fc_b[c];
        }
    }
}

// ================= launch =================
extern "C" void kernel_launch(void* const* d_in, const int* in_sizes, int n_in,
                              void* d_out, int out_size) {
    const int*   x    = (const int*)  d_in[0];
    const float* emb  = (const float*)d_in[1];
    const float* w1   = (const float*)d_in[2];
    const float* b1   = (const float*)d_in[3];
    const float* fc_w = (const float*)d_in[4];
    const float* fc_b = (const float*)d_in[5];
    float* out = (float*)d_out;

    dim3 g1(H_/64, M_/128);
    xin_kernel<<<g1, 256>>>(x, emb, w1, b1);

    cudaFuncSetAttribute(recur_kernel, cudaFuncAttributeMaxDynamicSharedMemorySize, S_TOTAL);
    recur_kernel<<<GRID_G, 256, S_TOTAL>>>(w1, out + YSIZE);

    fc_kernel<<<C_/64, 256>>>(fc_w, fc_b, out);
}

// round 7
// speedup vs baseline: 3.4787x; 1.1363x over previous
#include <cuda_runtime.h>
#include <cuda_bf16.h>
#include <math.h>
#include <stdint.h>

// Problem constants
#define T_    512
#define B_    64
#define H_    1024
#define C_    32000
#define SIXH  6144
#define M_    (T_*B_)
#define BH    (B_*H_)
#define YSIZE (B_*C_)
#define GRID_G 128

// -------- scratch --------
__device__ float    g_xin[M_*H_];
__device__ float    g_h[BH];
__device__ float    g_part[8*BH];
__device__ __nv_bfloat16 g_xe_hi[M_*H_];   // gathered embedding, bf16 hi
__device__ __nv_bfloat16 g_xe_lo[M_*H_];   // bf16 lo (residual)
__device__ __nv_bfloat16 g_wx_hi[H_*H_];   // Wx^T as [n][k]
__device__ __nv_bfloat16 g_wx_lo[H_*H_];
__device__ unsigned g_bar   = 0;
__device__ unsigned g_epoch = 0;

// -------- grid barrier: REDG arrival + acquire poll (round-4 proven) --------
__device__ __forceinline__ void gsync(unsigned idx) {
    __syncthreads();
    if (threadIdx.x == 0) {
        asm volatile("red.release.gpu.global.add.u32 [%0], %1;"
                     :: "l"(&g_bar), "r"(1u) : "memory");
        const unsigned target = idx * GRID_G;
        unsigned v;
        do {
            asm volatile("ld.acquire.gpu.global.u32 %0, [%1];"
                         : "=r"(v) : "l"(&g_bar) : "memory");
        } while (v < target);
    }
    __syncthreads();
}

__device__ __forceinline__ uint32_t smem_u32(const void* p) {
    uint32_t a;
    asm("{ .reg .u64 t; cvta.to.shared.u64 t, %1; cvt.u32.u64 %0, t; }" : "=r"(a) : "l"(p));
    return a;
}
__device__ __forceinline__ void ldsm4(uint32_t* r, uint32_t a) {
    asm volatile("ldmatrix.sync.aligned.m8n8.x4.shared.b16 {%0,%1,%2,%3}, [%4];"
        : "=r"(r[0]), "=r"(r[1]), "=r"(r[2]), "=r"(r[3]) : "r"(a));
}
__device__ __forceinline__ void ldsm2(uint32_t* r, uint32_t a) {
    asm volatile("ldmatrix.sync.aligned.m8n8.x2.shared.b16 {%0,%1}, [%2];"
        : "=r"(r[0]), "=r"(r[1]) : "r"(a));
}
__device__ __forceinline__ void mma_bf16(float* d, const uint32_t* a, const uint32_t* b) {
    asm volatile("mma.sync.aligned.m16n8k16.row.col.f32.bf16.bf16.f32 "
        "{%0,%1,%2,%3}, {%4,%5,%6,%7}, {%8,%9}, {%0,%1,%2,%3};"
        : "+f"(d[0]), "+f"(d[1]), "+f"(d[2]), "+f"(d[3])
        : "r"(a[0]), "r"(a[1]), "r"(a[2]), "r"(a[3]), "r"(b[0]), "r"(b[1]));
}
__device__ __forceinline__ void split_bf16(float v, __nv_bfloat16& hi, __nv_bfloat16& lo) {
    hi = __float2bfloat16(v);
    lo = __float2bfloat16(v - __bfloat162float(hi));
}

// ================= Prepass A: xe = emb[x] -> bf16 hi/lo =================
// grid 4096, 256 thr: 8 rows/CTA, 1 float4 per thread per row.
__global__ void conv_xe_kernel(const int* __restrict__ x, const float* __restrict__ emb) {
    const int tid = threadIdx.x;
    #pragma unroll
    for (int it = 0; it < 8; it++) {
        int r = blockIdx.x * 8 + it;
        int token = __ldg(&x[r]);
        float4 v = *(const float4*)&emb[(size_t)token * H_ + tid * 4];
        __nv_bfloat16 hx, lx, hy, ly, hz, lz, hw, lw;
        split_bf16(v.x, hx, lx); split_bf16(v.y, hy, ly);
        split_bf16(v.z, hz, lz); split_bf16(v.w, hw, lw);
        size_t o = (size_t)r * H_ + tid * 4;
        *(__nv_bfloat162*)&g_xe_hi[o]     = __halves2bfloat162(hx, hy);
        *(__nv_bfloat162*)&g_xe_hi[o + 2] = __halves2bfloat162(hz, hw);
        *(__nv_bfloat162*)&g_xe_lo[o]     = __halves2bfloat162(lx, ly);
        *(__nv_bfloat162*)&g_xe_lo[o + 2] = __halves2bfloat162(lz, lw);
    }
}

// ================= Prepass B: Wx -> bf16 hi/lo, transposed [n][k] =================
// grid 1024 (one n per CTA), 256 thr over k.
__global__ void conv_wx_kernel(const float* __restrict__ w1) {
    const int n = blockIdx.x;
    for (int k = threadIdx.x; k < H_; k += 256) {
        float v = w1[(size_t)k * SIXH + n];
        __nv_bfloat16 hi, lo;
        split_bf16(v, hi, lo);
        g_wx_hi[n * H_ + k] = hi;
        g_wx_lo[n * H_ + k] = lo;
    }
}

// ================= Kernel 1: xin = xe @ Wx + b  (bf16 3-split mma) =================
// CTA 128x128, 8 warps (mw 0..3 x nw 0..1), warp tile 32x64. K chunks of 64.
#define XSTR 144                   // smem row stride (bytes): conflict-free for ldmatrix
#define SA_HI 0
#define SA_LO (128*XSTR)
#define SB_HI (2*128*XSTR)
#define SB_LO (3*128*XSTR)
#define XS_TOTAL (4*128*XSTR)      // 73728 B
__global__ void __launch_bounds__(256, 2)
xin_mma_kernel(const float* __restrict__ b1) {
    extern __shared__ __align__(16) char smem[];
    const uint32_t sb = smem_u32(smem);
    const int tid = threadIdx.x;
    const int wid = tid >> 5, l = tid & 31;
    const int mw = wid & 3, nw = wid >> 2;
    const int n0 = blockIdx.x * 128;
    const int r0 = blockIdx.y * 128;

    // ldmatrix bases (offsets within chunk added per k-step)
    const uint32_t a_row = (uint32_t)(mw*32 + (l & 7) + ((l >> 3) & 1) * 8);
    const uint32_t a_off = a_row * XSTR + ((l >> 4) & 1) * 16;
    const uint32_t b_row = (uint32_t)(nw*64 + (l & 7));
    const uint32_t b_off = b_row * XSTR + ((l >> 3) & 1) * 16;

    float d[2][8][4] = {};
    for (int kc = 0; kc < 16; kc++) {
        __syncthreads();
        // stage A/B hi+lo chunk: [128 rows][64 k] bf16 each; 4 uint4 per thread per matrix
        #pragma unroll
        for (int it = 0; it < 4; it++) {
            int f = tid + it * 256;           // 1024 uint4 per matrix
            int r = f >> 3, q = f & 7;
            size_t ga = (size_t)(r0 + r) * H_ + kc*64 + q*8;
            size_t gb = (size_t)(n0 + r) * H_ + kc*64 + q*8;
            *(uint4*)(smem + SA_HI + r*XSTR + q*16) = *(const uint4*)&g_xe_hi[ga];
            *(uint4*)(smem + SA_LO + r*XSTR + q*16) = *(const uint4*)&g_xe_lo[ga];
            *(uint4*)(smem + SB_HI + r*XSTR + q*16) = *(const uint4*)&g_wx_hi[gb];
            *(uint4*)(smem + SB_LO + r*XSTR + q*16) = *(const uint4*)&g_wx_lo[gb];
        }
        __syncthreads();
        #pragma unroll
        for (int s = 0; s < 4; s++) {
            uint32_t ahi[2][4], alo[2][4];
            #pragma unroll
            for (int i = 0; i < 2; i++) {
                uint32_t ao = a_off + (uint32_t)(i * 16 * XSTR) + s * 32;
                ldsm4(ahi[i], sb + SA_HI + ao);
                ldsm4(alo[i], sb + SA_LO + ao);
            }
            #pragma unroll
            for (int ns = 0; ns < 8; ns++) {
                uint32_t bhi[2], blo[2];
                uint32_t bo = b_off + (uint32_t)(ns * 8 * XSTR) + s * 32;
                ldsm2(bhi, sb + SB_HI + bo);
                ldsm2(blo, sb + SB_LO + bo);
                #pragma unroll
                for (int i = 0; i < 2; i++) {
                    mma_bf16(d[i][ns], ahi[i], bhi);
                    mma_bf16(d[i][ns], ahi[i], blo);
                    mma_bf16(d[i][ns], alo[i], bhi);
                }
            }
        }
    }
    // epilogue: + bias, fp32 store
    #pragma unroll
    for (int i = 0; i < 2; i++) {
        int row = r0 + mw*32 + i*16 + (l >> 2);
        #pragma unroll
        for (int ns = 0; ns < 8; ns++) {
            int col = n0 + nw*64 + ns*8 + (l & 3) * 2;
            float2 bb = *(const float2*)&b1[col];
            *(float2*)&g_xin[(size_t)row * H_ + col] =
                make_float2(d[i][ns][0] + bb.x, d[i][ns][1] + bb.y);
            *(float2*)&g_xin[(size_t)(row + 8) * H_ + col] =
                make_float2(d[i][ns][2] + bb.x, d[i][ns][3] + bb.y);
        }
    }
}

// ================= Kernel 2: persistent recurrence (round-6, unchanged) ==========
#define RSTR   272
#define S_AHI  0
#define S_ALO  (64*RSTR)
#define S_BHI  (2*64*RSTR)
#define S_BLO  (3*64*RSTR)
#define S_TOTAL (4*64*RSTR)

__global__ void __launch_bounds__(256, 1)
recur_kernel(const float* __restrict__ w1, float* __restrict__ out_hist) {
    extern __shared__ __align__(1024) char smem[];
    const uint32_t sb = smem_u32(smem);
    const int tid = threadIdx.x;
    const int wid = tid >> 5;
    const int l   = tid & 31;
    const int bx  = blockIdx.x;
    const int nt = bx >> 3, ks = bx & 7;
    const int m  = wid & 3;
    const int nh = wid >> 2;

    unsigned idx = __ldcg(&g_epoch);

    #pragma unroll
    for (int it = 0; it < 8; it++) {
        int f = tid + it * 256;
        int k = f >> 4, nq = (f & 15) * 4;
        float4 v = *(const float4*)&w1[(ks*128 + k) * SIXH + H_ + nt*64 + nq];
        float vv[4] = {v.x, v.y, v.z, v.w};
        #pragma unroll
        for (int q = 0; q < 4; q++) {
            int off = (nq + q) * RSTR + k * 2;
            __nv_bfloat16 hi, lo;
            split_bf16(vv[q], hi, lo);
            *(__nv_bfloat16*)(smem + S_BHI + off) = hi;
            *(__nv_bfloat16*)(smem + S_BLO + off) = lo;
        }
    }

    #pragma unroll
    for (int i = 0; i < 2; i++) {
        int e = bx * 512 + i * 256 + tid;
        float v = tanhf(g_xin[e]);
        g_h[e] = v;
        out_hist[(e >> 10) * (T_*H_) + (e & 1023)] = v;
    }
    gsync(++idx);

    const uint32_t a_addr0 = sb + (uint32_t)((m*16 + (l & 7) + ((l >> 3) & 1) * 8) * RSTR
                                             + ((l >> 4) & 1) * 16);
    const uint32_t b_addr0 = sb + (uint32_t)((nh*32 + (l & 7)) * RSTR + ((l >> 3) & 1) * 16);

    auto convert_h = [&]() {
        int b = tid >> 2, c0 = (tid & 3) * 32;
        #pragma unroll
        for (int i = 0; i < 8; i++) {
            int c = c0 + i * 4;
            float4 v = __ldcg((const float4*)&g_h[b * H_ + ks*128 + c]);
            int off = b * RSTR + c * 2;
            __nv_bfloat16 hx, lx, hy, ly, hz, lz, hw, lw;
            split_bf16(v.x, hx, lx); split_bf16(v.y, hy, ly);
            split_bf16(v.z, hz, lz); split_bf16(v.w, hw, lw);
            *(__nv_bfloat162*)(smem + S_AHI + off)     = __halves2bfloat162(hx, hy);
            *(__nv_bfloat162*)(smem + S_AHI + off + 4) = __halves2bfloat162(hz, hw);
            *(__nv_bfloat162*)(smem + S_ALO + off)     = __halves2bfloat162(lx, ly);
            *(__nv_bfloat162*)(smem + S_ALO + off + 4) = __halves2bfloat162(lz, lw);
        }
    };
    convert_h();
    __syncthreads();

    for (int t = 1; t < T_; t++) {
        for (int j = 0; j < 2; j++) {
            float d[4][4] = {};
            #pragma unroll
            for (int s = 0; s < 8; s++) {
                uint32_t a_hi[4], a_lo[4];
                ldsm4(a_hi, a_addr0 + S_AHI + s * 32);
                ldsm4(a_lo, a_addr0 + S_ALO + s * 32);
                #pragma unroll
                for (int ns = 0; ns < 4; ns++) {
                    uint32_t b_hi[2], b_lo[2];
                    uint32_t bo = b_addr0 + (uint32_t)(ns * 8 * RSTR) + s * 32;
                    ldsm2(b_hi, bo + S_BHI);
                    ldsm2(b_lo, bo + S_BLO);
                    mma_bf16(d[ns], a_hi, b_hi);
                    mma_bf16(d[ns], a_hi, b_lo);
                    mma_bf16(d[ns], a_lo, b_hi);
                }
            }
            {
                int row0 = m*16 + (l >> 2);
                int gcol = nt*64 + nh*32 + (l & 3) * 2;
                float* p = &g_part[ks*BH + row0*H_ + gcol];
                #pragma unroll
                for (int ns = 0; ns < 4; ns++) {
                    *(float2*)(p + ns*8)          = make_float2(d[ns][0], d[ns][1]);
                    *(float2*)(p + ns*8 + 8*H_)   = make_float2(d[ns][2], d[ns][3]);
                }
            }
            float2 xp = __ldcg((const float2*)&g_xin[t*BH + bx*512] + tid);
            gsync(++idx);

            const bool wr = (j == 1);
            {
                float2 s = xp;
                #pragma unroll
                for (int p = 0; p < 8; p++) {
                    float2 pv = __ldcg((const float2*)&g_part[p*BH + bx*512] + tid);
                    s.x += pv.x; s.y += pv.y;
                }
                float2 v = make_float2(tanhf(s.x), tanhf(s.y));
                int e = bx * 512 + tid * 2;
                *(float2*)&g_h[e] = v;
                if (wr) *(float2*)&out_hist[(e >> 10) * (T_*H_) + t * H_ + (e & 1023)] = v;
            }
            if (t == T_-1 && j == 1) break;
            gsync(++idx);

            convert_h();
            __syncthreads();
        }
    }
    if (bx == 0 && tid == 0) g_epoch = idx;
}

// ================= Kernel 3: y = h_last @ fc_w^T + fc_b (unchanged) ==========
__global__ void fc_kernel(const float* __restrict__ fc_w, const float* __restrict__ fc_b,
                          float* __restrict__ y) {
    __shared__ __align__(16) float As[64*16];
    __shared__ __align__(16) float Bs[16*64];
    const int tid = threadIdx.x;
    const int c0 = blockIdx.x * 64;
    const int tx = tid & 15, ty = tid >> 4;

    float acc[4][4] = {};
    for (int k0 = 0; k0 < H_; k0 += 16) {
        #pragma unroll
        for (int j = 0; j < 4; j++) {
            int f = tid + j * 256;
            int row = f >> 4, kk = f & 15;
            As[row * 16 + kk] = g_h[row * H_ + k0 + kk];
            Bs[kk * 64 + row] = fc_w[(c0 + row) * H_ + k0 + kk];
        }
        __syncthreads();
        #pragma unroll
        for (int kk = 0; kk < 16; kk++) {
            float a0 = As[(ty*4+0)*16 + kk];
            float a1 = As[(ty*4+1)*16 + kk];
            float a2 = As[(ty*4+2)*16 + kk];
            float a3 = As[(ty*4+3)*16 + kk];
            float4 bv = *(const float4*)&Bs[kk*64 + tx*4];
            acc[0][0] += a0*bv.x; acc[0][1] += a0*bv.y; acc[0][2] += a0*bv.z; acc[0][3] += a0*bv.w;
            acc[1][0] += a1*bv.x; acc[1][1] += a1*bv.y; acc[1][2] += a1*bv.z; acc[1][3] += a1*bv.w;
            acc[2][0] += a2*bv.x; acc[2][1] += a2*bv.y; acc[2][2] += a2*bv.z; acc[2][3] += a2*bv.w;
            acc[3][0] += a3*bv.x; acc[3][1] += a3*bv.y; acc[3][2] += a3*bv.z; acc[3][3] += a3*bv.w;
        }
        __syncthreads();
    }
    #pragma unroll
    for (int i = 0; i < 4; i++) {
        #pragma unroll
        for (int j = 0; j < 4; j++) {
            int c = c0 + tx*4 + j;
            y[(ty*4 + i) * C_ + c] = acc[i][j] + fc_b[c];
        }
    }
}

// ================= launch =================
extern "C" void kernel_launch(void* const* d_in, const int* in_sizes, int n_in,
                              void* d_out, int out_size) {
    const int*   x    = (const int*)  d_in[0];
    const float* emb  = (const float*)d_in[1];
    const float* w1   = (const float*)d_in[2];
    const float* b1   = (const float*)d_in[3];
    const float* fc_w = (const float*)d_in[4];
    const float* fc_b = (const float*)d_in[5];
    float* out = (float*)d_out;

    conv_wx_kernel<<<H_, 256>>>(w1);
    conv_xe_kernel<<<M_/8, 256>>>(x, emb);

    dim3 gx(H_/128, M_/128);
    cudaFuncSetAttribute(xin_mma_kernel, cudaFuncAttributeMaxDynamicSharedMemorySize, XS_TOTAL);
    xin_mma_kernel<<<gx, 256, XS_TOTAL>>>(b1);

    cudaFuncSetAttribute(recur_kernel, cudaFuncAttributeMaxDynamicSharedMemorySize, S_TOTAL);
    recur_kernel<<<GRID_G, 256, S_TOTAL>>>(w1, out + YSIZE);

    fc_kernel<<<C_/64, 256>>>(fc_w, fc_b, out);
}

// round 8
// speedup vs baseline: 4.5222x; 1.3000x over previous
#include <cuda_runtime.h>
#include <cuda_bf16.h>
#include <math.h>
#include <stdint.h>

// Problem constants
#define T_    512
#define B_    64
#define H_    1024
#define C_    32000
#define SIXH  6144
#define M_    (T_*B_)
#define BH    (B_*H_)
#define YSIZE (B_*C_)
#define GRID_G 128
#define NSTEP 1022            // inner steps s=1..1022 (plus prologue s=0)

// -------- scratch --------
__device__ float    g_xin[M_*H_];
__device__ float    g_part2[2][8*BH];           // double-buffered K-split partials
__device__ __nv_bfloat16 g_hh[2][BH];           // h hi, ping-pong
__device__ __nv_bfloat16 g_hl[2][BH];           // h lo, ping-pong
__device__ __nv_bfloat16 g_xe_hi[M_*H_];
__device__ __nv_bfloat16 g_xe_lo[M_*H_];
__device__ __nv_bfloat16 g_wx_hi[H_*H_];
__device__ __nv_bfloat16 g_wx_lo[H_*H_];
__device__ __nv_bfloat16 g_fcw_hi[(size_t)C_*H_];
__device__ __nv_bfloat16 g_fcw_lo[(size_t)C_*H_];
__device__ unsigned g_pairc[8];                 // parts-written counters (16 arrivals/step)
__device__ unsigned g_famc[8];                  // reduce-done counters  (16 arrivals/step)
__device__ unsigned g_epoch = 0;                // total steps completed across replays

__device__ __forceinline__ void arrive_cnt(unsigned* c) {
    asm volatile("red.release.gpu.global.add.u32 [%0], %1;" :: "l"(c), "r"(1u) : "memory");
}
__device__ __forceinline__ void wait_cnt(unsigned* c, unsigned target) {
    unsigned v;
    do { asm volatile("ld.acquire.gpu.global.u32 %0, [%1];" : "=r"(v) : "l"(c) : "memory"); }
    while (v < target);
}

__device__ __forceinline__ uint32_t smem_u32(const void* p) {
    uint32_t a;
    asm("{ .reg .u64 t; cvta.to.shared.u64 t, %1; cvt.u32.u64 %0, t; }" : "=r"(a) : "l"(p));
    return a;
}
__device__ __forceinline__ void ldsm4(uint32_t* r, uint32_t a) {
    asm volatile("ldmatrix.sync.aligned.m8n8.x4.shared.b16 {%0,%1,%2,%3}, [%4];"
        : "=r"(r[0]), "=r"(r[1]), "=r"(r[2]), "=r"(r[3]) : "r"(a));
}
__device__ __forceinline__ void ldsm2(uint32_t* r, uint32_t a) {
    asm volatile("ldmatrix.sync.aligned.m8n8.x2.shared.b16 {%0,%1}, [%2];"
        : "=r"(r[0]), "=r"(r[1]) : "r"(a));
}
__device__ __forceinline__ void mma_bf16(float* d, const uint32_t* a, const uint32_t* b) {
    asm volatile("mma.sync.aligned.m16n8k16.row.col.f32.bf16.bf16.f32 "
        "{%0,%1,%2,%3}, {%4,%5,%6,%7}, {%8,%9}, {%0,%1,%2,%3};"
        : "+f"(d[0]), "+f"(d[1]), "+f"(d[2]), "+f"(d[3])
        : "r"(a[0]), "r"(a[1]), "r"(a[2]), "r"(a[3]), "r"(b[0]), "r"(b[1]));
}
__device__ __forceinline__ void split_bf16(float v, __nv_bfloat16& hi, __nv_bfloat16& lo) {
    hi = __float2bfloat16(v);
    lo = __float2bfloat16(v - __bfloat162float(hi));
}

// ================= Prepass A: xe = emb[x] -> bf16 hi/lo =================
__global__ void conv_xe_kernel(const int* __restrict__ x, const float* __restrict__ emb) {
    const int tid = threadIdx.x;
    #pragma unroll
    for (int it = 0; it < 8; it++) {
        int r = blockIdx.x * 8 + it;
        int token = __ldg(&x[r]);
        float4 v = *(const float4*)&emb[(size_t)token * H_ + tid * 4];
        __nv_bfloat16 hx, lx, hy, ly, hz, lz, hw, lw;
        split_bf16(v.x, hx, lx); split_bf16(v.y, hy, ly);
        split_bf16(v.z, hz, lz); split_bf16(v.w, hw, lw);
        size_t o = (size_t)r * H_ + tid * 4;
        *(__nv_bfloat162*)&g_xe_hi[o]     = __halves2bfloat162(hx, hy);
        *(__nv_bfloat162*)&g_xe_hi[o + 2] = __halves2bfloat162(hz, hw);
        *(__nv_bfloat162*)&g_xe_lo[o]     = __halves2bfloat162(lx, ly);
        *(__nv_bfloat162*)&g_xe_lo[o + 2] = __halves2bfloat162(lz, lw);
    }
}

// ================= Prepass B: Wx -> bf16 hi/lo transposed [n][k] =================
__global__ void conv_wx_kernel(const float* __restrict__ w1) {
    const int n = blockIdx.x;
    for (int k = threadIdx.x; k < H_; k += 256) {
        float v = w1[(size_t)k * SIXH + n];
        __nv_bfloat16 hi, lo;
        split_bf16(v, hi, lo);
        g_wx_hi[n * H_ + k] = hi;
        g_wx_lo[n * H_ + k] = lo;
    }
}

// ================= Prepass C: fc_w -> bf16 hi/lo (same [c][k] layout) =================
__global__ void conv_fcw_kernel(const float* __restrict__ fc_w) {
    const int tid = threadIdx.x;
    #pragma unroll
    for (int it = 0; it < 8; it++) {
        size_t r = (size_t)blockIdx.x * 8 + it;
        float4 v = *(const float4*)&fc_w[r * H_ + tid * 4];
        __nv_bfloat16 hx, lx, hy, ly, hz, lz, hw, lw;
        split_bf16(v.x, hx, lx); split_bf16(v.y, hy, ly);
        split_bf16(v.z, hz, lz); split_bf16(v.w, hw, lw);
        size_t o = r * H_ + tid * 4;
        *(__nv_bfloat162*)&g_fcw_hi[o]     = __halves2bfloat162(hx, hy);
        *(__nv_bfloat162*)&g_fcw_hi[o + 2] = __halves2bfloat162(hz, hw);
        *(__nv_bfloat162*)&g_fcw_lo[o]     = __halves2bfloat162(lx, ly);
        *(__nv_bfloat162*)&g_fcw_lo[o + 2] = __halves2bfloat162(lz, lw);
    }
}

// ================= Kernel 1: xin = xe @ Wx + b (round-7 proven, unchanged) ==========
#define XSTR 144
#define SA_HI 0
#define SA_LO (128*XSTR)
#define SB_HI (2*128*XSTR)
#define SB_LO (3*128*XSTR)
#define XS_TOTAL (4*128*XSTR)
__global__ void __launch_bounds__(256, 2)
xin_mma_kernel(const float* __restrict__ b1) {
    extern __shared__ __align__(16) char smem[];
    const uint32_t sb = smem_u32(smem);
    const int tid = threadIdx.x;
    const int wid = tid >> 5, l = tid & 31;
    const int mw = wid & 3, nw = wid >> 2;
    const int n0 = blockIdx.x * 128;
    const int r0 = blockIdx.y * 128;

    const uint32_t a_row = (uint32_t)(mw*32 + (l & 7) + ((l >> 3) & 1) * 8);
    const uint32_t a_off = a_row * XSTR + ((l >> 4) & 1) * 16;
    const uint32_t b_row = (uint32_t)(nw*64 + (l & 7));
    const uint32_t b_off = b_row * XSTR + ((l >> 3) & 1) * 16;

    float d[2][8][4] = {};
    for (int kc = 0; kc < 16; kc++) {
        __syncthreads();
        #pragma unroll
        for (int it = 0; it < 4; it++) {
            int f = tid + it * 256;
            int r = f >> 3, q = f & 7;
            size_t ga = (size_t)(r0 + r) * H_ + kc*64 + q*8;
            size_t gb = (size_t)(n0 + r) * H_ + kc*64 + q*8;
            *(uint4*)(smem + SA_HI + r*XSTR + q*16) = *(const uint4*)&g_xe_hi[ga];
            *(uint4*)(smem + SA_LO + r*XSTR + q*16) = *(const uint4*)&g_xe_lo[ga];
            *(uint4*)(smem + SB_HI + r*XSTR + q*16) = *(const uint4*)&g_wx_hi[gb];
            *(uint4*)(smem + SB_LO + r*XSTR + q*16) = *(const uint4*)&g_wx_lo[gb];
        }
        __syncthreads();
        #pragma unroll
        for (int s = 0; s < 4; s++) {
            uint32_t ahi[2][4], alo[2][4];
            #pragma unroll
            for (int i = 0; i < 2; i++) {
                uint32_t ao = a_off + (uint32_t)(i * 16 * XSTR) + s * 32;
                ldsm4(ahi[i], sb + SA_HI + ao);
                ldsm4(alo[i], sb + SA_LO + ao);
            }
            #pragma unroll
            for (int ns = 0; ns < 8; ns++) {
                uint32_t bhi[2], blo[2];
                uint32_t bo = b_off + (uint32_t)(ns * 8 * XSTR) + s * 32;
                ldsm2(bhi, sb + SB_HI + bo);
                ldsm2(blo, sb + SB_LO + bo);
                #pragma unroll
                for (int i = 0; i < 2; i++) {
                    mma_bf16(d[i][ns], ahi[i], bhi);
                    mma_bf16(d[i][ns], ahi[i], blo);
                    mma_bf16(d[i][ns], alo[i], bhi);
                }
            }
        }
    }
    #pragma unroll
    for (int i = 0; i < 2; i++) {
        int row = r0 + mw*32 + i*16 + (l >> 2);
        #pragma unroll
        for (int ns = 0; ns < 8; ns++) {
            int col = n0 + nw*64 + ns*8 + (l & 3) * 2;
            float2 bb = *(const float2*)&b1[col];
            *(float2*)&g_xin[(size_t)row * H_ + col] =
                make_float2(d[i][ns][0] + bb.x, d[i][ns][1] + bb.y);
            *(float2*)&g_xin[(size_t)(row + 8) * H_ + col] =
                make_float2(d[i][ns][2] + bb.x, d[i][ns][3] + bb.y);
        }
    }
}

// ================= Kernel 2: persistent recurrence, 16-CTA dependency barriers ========
// CTA (nt,ks): nt = bx>>3 (64-col N tile), ks = bx&7 (128-row K slice).
// Reduce chunk: b in [4nt,4nt+4), n in [128ks,128ks+128)  => needs parts from nts {2ks,2ks+1}
// GEMM A slice: h[:, 128ks..+128)                         => needs h from family ks
#define RSTR   272
#define S_AHI  0
#define S_ALO  (64*RSTR)
#define S_BHI  (2*64*RSTR)
#define S_BLO  (3*64*RSTR)
#define S_TOTAL (4*64*RSTR)

__global__ void __launch_bounds__(256, 1)
recur_kernel(const float* __restrict__ w1, float* __restrict__ out_hist) {
    extern __shared__ __align__(1024) char smem[];
    const uint32_t sb = smem_u32(smem);
    const int tid = threadIdx.x;
    const int wid = tid >> 5;
    const int l   = tid & 31;
    const int bx  = blockIdx.x;
    const int nt = bx >> 3, ks = bx & 7;
    const int m  = wid & 3;
    const int nh = wid >> 2;

    const unsigned E = __ldcg(&g_epoch);

    // resident Wh slab -> Bhi/Blo[n][k] bf16
    #pragma unroll
    for (int it = 0; it < 8; it++) {
        int f = tid + it * 256;
        int k = f >> 4, nq = (f & 15) * 4;
        float4 v = *(const float4*)&w1[(ks*128 + k) * SIXH + H_ + nt*64 + nq];
        float vv[4] = {v.x, v.y, v.z, v.w};
        #pragma unroll
        for (int q = 0; q < 4; q++) {
            int off = (nq + q) * RSTR + k * 2;
            __nv_bfloat16 hi, lo;
            split_bf16(vv[q], hi, lo);
            *(__nv_bfloat16*)(smem + S_BHI + off) = hi;
            *(__nv_bfloat16*)(smem + S_BLO + off) = lo;
        }
    }

    // reduce-chunk coords for this CTA
    const int b_r = nt*4 + (tid >> 6);           // batch row
    const int n_r = ks*128 + (tid & 63) * 2;     // output column (float2)

    // prologue (s=0): h0 = tanh(xin[0]) on own chunk -> hbuf[0] (+hist t=0)
    {
        float2 xv = *(const float2*)&g_xin[b_r * H_ + n_r];
        float2 v = make_float2(tanhf(xv.x), tanhf(xv.y));
        __nv_bfloat16 hx, lx, hy, ly;
        split_bf16(v.x, hx, lx); split_bf16(v.y, hy, ly);
        *(__nv_bfloat162*)&g_hh[0][b_r * H_ + n_r] = __halves2bfloat162(hx, hy);
        *(__nv_bfloat162*)&g_hl[0][b_r * H_ + n_r] = __halves2bfloat162(lx, ly);
        *(float2*)&out_hist[(size_t)b_r * (T_*H_) + n_r] = v;
    }
    __syncthreads();
    if (tid == 0) { arrive_cnt(&g_famc[ks]); arrive_cnt(&g_pairc[nt >> 1]); }

    // ldmatrix bases
    const uint32_t a_addr0 = sb + (uint32_t)((m*16 + (l & 7) + ((l >> 3) & 1) * 8) * RSTR
                                             + ((l >> 4) & 1) * 16);
    const uint32_t b_addr0 = sb + (uint32_t)((nh*32 + (l & 7)) * RSTR + ((l >> 3) & 1) * 16);

    for (int s = 1; s <= NSTEP; s++) {
        // ---- wait h_{s-1} from family ks, stage A (plain bf16 copy) ----
        if (tid == 0) wait_cnt(&g_famc[ks], (E + (unsigned)s) * 16u);
        __syncthreads();
        {
            const __nv_bfloat16* hsrc_h = g_hh[(s-1) & 1];
            const __nv_bfloat16* hsrc_l = g_hl[(s-1) & 1];
            #pragma unroll
            for (int it = 0; it < 8; it++) {
                int f = tid + it * 256;              // 2048: buf(2) x row(64) x q(16)
                int buf = f >> 10, g = f & 1023;
                int row = g >> 4, q = g & 15;
                const __nv_bfloat16* src = (buf ? hsrc_l : hsrc_h) + row * H_ + ks*128 + q*8;
                char* dst = smem + (buf ? S_ALO : S_AHI) + row * RSTR + q * 16;
                *(uint4*)dst = __ldcg((const uint4*)src);
            }
        }
        __syncthreads();

        // ---- GEMM: parts[s&1][ks][b][nt cols] ----
        float d[4][4] = {};
        #pragma unroll
        for (int ss = 0; ss < 8; ss++) {
            uint32_t a_hi[4], a_lo[4];
            ldsm4(a_hi, a_addr0 + S_AHI + ss * 32);
            ldsm4(a_lo, a_addr0 + S_ALO + ss * 32);
            #pragma unroll
            for (int ns = 0; ns < 4; ns++) {
                uint32_t b_hi[2], b_lo[2];
                uint32_t bo = b_addr0 + (uint32_t)(ns * 8 * RSTR) + ss * 32;
                ldsm2(b_hi, bo + S_BHI);
                ldsm2(b_lo, bo + S_BLO);
                mma_bf16(d[ns], a_hi, b_hi);
                mma_bf16(d[ns], a_hi, b_lo);
                mma_bf16(d[ns], a_lo, b_hi);
            }
        }
        {
            float* pb = g_part2[s & 1];
            int row0 = m*16 + (l >> 2);
            int gcol = nt*64 + nh*32 + (l & 3) * 2;
            float* p = &pb[ks*BH + row0*H_ + gcol];
            #pragma unroll
            for (int ns = 0; ns < 4; ns++) {
                *(float2*)(p + ns*8)        = make_float2(d[ns][0], d[ns][1]);
                *(float2*)(p + ns*8 + 8*H_) = make_float2(d[ns][2], d[ns][3]);
            }
        }
        __syncthreads();
        if (tid == 0) arrive_cnt(&g_pairc[nt >> 1]);

        // prefetch xin for reduce
        const int t = (s + 1) >> 1;
        float2 xp = __ldcg((const float2*)&g_xin[(size_t)t * BH + b_r * H_ + n_r]);

        // ---- wait parts from nts {2ks,2ks+1}, reduce own chunk ----
        if (tid == 0) wait_cnt(&g_pairc[ks], (E + (unsigned)s + 1u) * 16u);
        __syncthreads();
        {
            const float* pb = g_part2[s & 1];
            float2 acc = xp;
            #pragma unroll
            for (int p = 0; p < 8; p++) {
                float2 pv = __ldcg((const float2*)&pb[p*BH + b_r*H_ + n_r]);
                acc.x += pv.x; acc.y += pv.y;
            }
            float2 v = make_float2(tanhf(acc.x), tanhf(acc.y));
            __nv_bfloat16 hx, lx, hy, ly;
            split_bf16(v.x, hx, lx); split_bf16(v.y, hy, ly);
            *(__nv_bfloat162*)&g_hh[s & 1][b_r * H_ + n_r] = __halves2bfloat162(hx, hy);
            *(__nv_bfloat162*)&g_hl[s & 1][b_r * H_ + n_r] = __halves2bfloat162(lx, ly);
            if ((s & 1) == 0)
                *(float2*)&out_hist[(size_t)b_r * (T_*H_) + t * H_ + n_r] = v;
        }
        __syncthreads();
        if (tid == 0) arrive_cnt(&g_famc[ks]);
    }
    if (bx == 0 && tid == 0) g_epoch = E + (unsigned)(NSTEP + 1);
}

// ================= Kernel 3: y = h_last @ fc_w^T + fc_b (bf16 3-split mma) ==========
// CTA tile 64 x 256, 8 warps (2 mw x 4 nw), warp tile 32x64. A = h_last (g_hh/g_hl[0]).
#define FSTR 144
#define FA_HI 0
#define FA_LO (64*FSTR)
#define FB_HI (2*64*FSTR)
#define FB_LO (FB_HI + 256*FSTR)
#define FS_TOTAL (FB_LO + 256*FSTR)    // 92160 B
__global__ void __launch_bounds__(256, 1)
fc_mma_kernel(const float* __restrict__ fc_b, float* __restrict__ y) {
    extern __shared__ __align__(16) char smem[];
    const uint32_t sb = smem_u32(smem);
    const int tid = threadIdx.x;
    const int wid = tid >> 5, l = tid & 31;
    const int mw = wid & 1, nw = wid >> 1;
    const int c0 = blockIdx.x * 256;

    const uint32_t a_off = (uint32_t)((mw*32 + (l & 7) + ((l >> 3) & 1) * 8) * FSTR
                                      + ((l >> 4) & 1) * 16);
    const uint32_t b_off = (uint32_t)((nw*64 + (l & 7)) * FSTR + ((l >> 3) & 1) * 16);

    float d[2][8][4] = {};
    for (int kc = 0; kc < 16; kc++) {
        __syncthreads();
        // stage A: 64x64 hi+lo (1024 uint4 -> 4/thread)
        #pragma unroll
        for (int it = 0; it < 4; it++) {
            int f = tid + it * 256;
            int buf = f >> 9, g = f & 511;
            int row = g >> 3, q = g & 7;
            const __nv_bfloat16* src = (buf ? g_hl[0] : g_hh[0]) + row * H_ + kc*64 + q*8;
            *(uint4*)(smem + (buf ? FA_LO : FA_HI) + row*FSTR + q*16) = *(const uint4*)src;
        }
        // stage B: 256x64 hi+lo (4096 uint4 -> 16/thread)
        #pragma unroll
        for (int it = 0; it < 16; it++) {
            int f = tid + it * 256;
            int buf = f >> 11, g = f & 2047;
            int row = g >> 3, q = g & 7;
            const __nv_bfloat16* src = (buf ? g_fcw_lo : g_fcw_hi)
                                     + (size_t)(c0 + row) * H_ + kc*64 + q*8;
            *(uint4*)(smem + (buf ? FB_LO : FB_HI) + row*FSTR + q*16) = *(const uint4*)src;
        }
        __syncthreads();
        #pragma unroll
        for (int s = 0; s < 4; s++) {
            uint32_t ahi[2][4], alo[2][4];
            #pragma unroll
            for (int i = 0; i < 2; i++) {
                uint32_t ao = a_off + (uint32_t)(i * 16 * FSTR) + s * 32;
                ldsm4(ahi[i], sb + FA_HI + ao);
                ldsm4(alo[i], sb + FA_LO + ao);
            }
            #pragma unroll
            for (int ns = 0; ns < 8; ns++) {
                uint32_t bhi[2], blo[2];
                uint32_t bo = b_off + (uint32_t)(ns * 8 * FSTR) + s * 32;
                ldsm2(bhi, sb + FB_HI + bo);
                ldsm2(blo, sb + FB_LO + bo);
                #pragma unroll
                for (int i = 0; i < 2; i++) {
                    mma_bf16(d[i][ns], ahi[i], bhi);
                    mma_bf16(d[i][ns], ahi[i], blo);
                    mma_bf16(d[i][ns], alo[i], bhi);
                }
            }
        }
    }
    #pragma unroll
    for (int i = 0; i < 2; i++) {
        int row = mw*32 + i*16 + (l >> 2);
        #pragma unroll
        for (int ns = 0; ns < 8; ns++) {
            int col = c0 + nw*64 + ns*8 + (l & 3) * 2;
            float2 bb = *(const float2*)&fc_b[col];
            *(float2*)&y[(size_t)row * C_ + col] =
                make_float2(d[i][ns][0] + bb.x, d[i][ns][1] + bb.y);
            *(float2*)&y[(size_t)(row + 8) * C_ + col] =
                make_float2(d[i][ns][2] + bb.x, d[i][ns][3] + bb.y);
        }
    }
}

// ================= launch =================
extern "C" void kernel_launch(void* const* d_in, const int* in_sizes, int n_in,
                              void* d_out, int out_size) {
    const int*   x    = (const int*)  d_in[0];
    const float* emb  = (const float*)d_in[1];
    const float* w1   = (const float*)d_in[2];
    const float* b1   = (const float*)d_in[3];
    const float* fc_w = (const float*)d_in[4];
    const float* fc_b = (const float*)d_in[5];
    float* out = (float*)d_out;

    conv_wx_kernel<<<H_, 256>>>(w1);
    conv_xe_kernel<<<M_/8, 256>>>(x, emb);
    conv_fcw_kernel<<<C_/8, 256>>>(fc_w);

    dim3 gx(H_/128, M_/128);
    cudaFuncSetAttribute(xin_mma_kernel, cudaFuncAttributeMaxDynamicSharedMemorySize, XS_TOTAL);
    xin_mma_kernel<<<gx, 256, XS_TOTAL>>>(b1);

    cudaFuncSetAttribute(recur_kernel, cudaFuncAttributeMaxDynamicSharedMemorySize, S_TOTAL);
    recur_kernel<<<GRID_G, 256, S_TOTAL>>>(w1, out + YSIZE);

    cudaFuncSetAttribute(fc_mma_kernel, cudaFuncAttributeMaxDynamicSharedMemorySize, FS_TOTAL);
    fc_mma_kernel<<<C_/256, 256, FS_TOTAL>>>(fc_b, out);
}